// round 14
// baseline (speedup 1.0000x reference)
#include <cuda_runtime.h>
#include <cuda_fp16.h>
#include <math.h>

#define MAXNM1 511
#define MAXSP  (MAXNM1 + 2)
#define MAXSP2 (MAXSP * MAXSP)
#define MAXP   (MAXNM1 * MAXNM1)

// fp16 storage, fp32 compute.
// Messages stored PREMULTIPLIED by sqrt(phiE):  x = sqrt(phiE)*m (pow2-normed).
// Psi = phiP * prod_s sqrt(phiE_s);  u_s = sum E/x_s is already in the stored
// convention -> iterations carry NO edge-phi traffic. Pads hold sqrt(phiE).
__device__ uint2 g_Mh[2][4][MAXSP2];   // x messages, padded SoA planes
__device__ uint4 g_psi[2][MAXP];       // Psi as halves (8 states per entry)
__device__ double g_F;
__device__ unsigned g_ctr;

// ---------------------------------------------------------------------------
__device__ __forceinline__ float4 h4_to_f4(uint2 v) {
    union { unsigned u; __half2 h; } a, b;
    a.u = v.x; b.u = v.y;
    float2 fa = __half22float2(a.h), fb = __half22float2(b.h);
    return make_float4(fa.x, fa.y, fb.x, fb.y);
}
__device__ __forceinline__ uint2 f4_to_h4(float4 f) {
    union { unsigned u; __half2 h; } a, b;
    a.h = __floats2half2_rn(f.x, f.y);
    b.h = __floats2half2_rn(f.z, f.w);
    return make_uint2(a.u, b.u);
}

__device__ __forceinline__ float fast_logf(float x) {
    int ix = __float_as_int(x);
    int ex = (ix >> 23) - 127;
    float m = __int_as_float((ix & 0x007FFFFF) | 0x3F800000);
    if (m > 1.41421356f) { m *= 0.5f; ex += 1; }
    float f = m - 1.0f;
    float z = f * f;
    float p = 7.0376836292e-2f;
    p = fmaf(p, f, -1.1514610310e-1f);
    p = fmaf(p, f,  1.1676998740e-1f);
    p = fmaf(p, f, -1.2420140846e-1f);
    p = fmaf(p, f,  1.4249322787e-1f);
    p = fmaf(p, f, -1.6668057665e-1f);
    p = fmaf(p, f,  2.0000714765e-1f);
    p = fmaf(p, f, -2.4999993993e-1f);
    p = fmaf(p, f,  3.3333331174e-1f);
    p = p * z * f;
    p = fmaf(-0.5f, z, p);
    return fmaf((float)ex, 0.693147180559945f, f + p);
}

__device__ __forceinline__ float pow2_inv_scale(float Z) {
    int eb = (__float_as_int(Z) >> 23) & 0xFF;
    return __int_as_float((254 - eb) << 23);
}

__device__ __forceinline__ void block_add_F(float v) {
    #pragma unroll
    for (int o = 16; o; o >>= 1) v += __shfl_down_sync(0xffffffffu, v, o);
    __shared__ float sh[32];
    int lane = threadIdx.x & 31, w = threadIdx.x >> 5;
    if (lane == 0) sh[w] = v;
    __syncthreads();
    if (w == 0) {
        int nw = (blockDim.x + 31) >> 5;
        float s = (lane < nw) ? sh[lane] : 0.0f;
        #pragma unroll
        for (int o = 16; o; o >>= 1) s += __shfl_down_sync(0xffffffffu, s, o);
        if (lane == 0) atomicAdd(&g_F, (double)s);
    }
}

__device__ __forceinline__ float4 mul4(float4 a, float4 b) {
    return make_float4(a.x * b.x, a.y * b.y, a.z * b.z, a.w * b.w);
}
__device__ __forceinline__ float4 exph4f(float4 v) {
    return make_float4(__expf(0.5f * v.x), __expf(0.5f * v.y),
                       __expf(0.5f * v.z), __expf(0.5f * v.w));
}

__device__ __forceinline__ void psi_unpack_regs(uint4 q0, uint4 q1, float Phi[16]) {
    float4 a = h4_to_f4(make_uint2(q0.x, q0.y));
    float4 b = h4_to_f4(make_uint2(q0.z, q0.w));
    float4 c = h4_to_f4(make_uint2(q1.x, q1.y));
    float4 d = h4_to_f4(make_uint2(q1.z, q1.w));
    Phi[0]=a.x; Phi[1]=a.y; Phi[2]=a.z; Phi[3]=a.w;
    Phi[4]=b.x; Phi[5]=b.y; Phi[6]=b.z; Phi[7]=b.w;
    Phi[8]=c.x; Phi[9]=c.y; Phi[10]=c.z; Phi[11]=c.w;
    Phi[12]=d.x; Phi[13]=d.y; Phi[14]=d.z; Phi[15]=d.w;
}
__device__ __forceinline__ void psi_unpack(int p, float Phi[16]) {
    psi_unpack_regs(__ldg(&g_psi[0][p]), __ldg(&g_psi[1][p]), Phi);
}

// Core 16-state update: cavity x0..x3 + Psi -> normalized messages at offset q.
__device__ __forceinline__ void plaq_update(
    float4 N0, float4 N1, float4 N2, float4 N3, const float Phi[16],
    int dst, int q)
{
    float n0[4] = {N0.x, N0.y, N0.z, N0.w};
    float n1[4] = {N1.x, N1.y, N1.z, N1.w};
    float n2[4] = {N2.x, N2.y, N2.z, N2.w};
    float n3[4] = {N3.x, N3.y, N3.z, N3.w};
    float u0[4] = {0,0,0,0}, u1[4] = {0,0,0,0}, u2[4] = {0,0,0,0}, u3[4] = {0,0,0,0};
    #pragma unroll
    for (int a = 0; a < 2; a++)
    #pragma unroll
    for (int b = 0; b < 2; b++)
    #pragma unroll
    for (int c = 0; c < 2; c++)
    #pragma unroll
    for (int d = 0; d < 2; d++) {
        int idx = a * 8 + b * 4 + c * 2 + d;
        float ph = Phi[idx];
        float va = n0[a * 2 + b], vb = n1[c * 2 + d];
        float vc = n2[a * 2 + c], vd = n3[b * 2 + d];
        float q1 = ph * vc * vd;
        u0[a * 2 + b] = fmaf(q1, vb, u0[a * 2 + b]);
        u1[c * 2 + d] = fmaf(q1, va, u1[c * 2 + d]);
        float q2 = ph * va * vb;
        u2[a * 2 + c] = fmaf(q2, vd, u2[a * 2 + c]);
        u3[b * 2 + d] = fmaf(q2, vc, u3[b * 2 + d]);
    }
    {
        float Z = (u0[0]+u0[1]) + (u0[2]+u0[3]); float s = pow2_inv_scale(Z);
        g_Mh[dst][0][q] = f4_to_h4(make_float4(u0[0]*s, u0[1]*s, u0[2]*s, u0[3]*s));
    }
    {
        float Z = (u1[0]+u1[1]) + (u1[2]+u1[3]); float s = pow2_inv_scale(Z);
        g_Mh[dst][1][q] = f4_to_h4(make_float4(u1[0]*s, u1[1]*s, u1[2]*s, u1[3]*s));
    }
    {
        float Z = (u2[0]+u2[1]) + (u2[2]+u2[3]); float s = pow2_inv_scale(Z);
        g_Mh[dst][2][q] = f4_to_h4(make_float4(u2[0]*s, u2[1]*s, u2[2]*s, u2[3]*s));
    }
    {
        float Z = (u3[0]+u3[1]) + (u3[2]+u3[3]); float s = pow2_inv_scale(Z);
        g_Mh[dst][3][q] = f4_to_h4(make_float4(u3[0]*s, u3[1]*s, u3[2]*s, u3[3]*s));
    }
}

// ---------------------------------------------------------------------------
// ILP-1 iteration: ONE plaquette per thread -> 2044 blocks, 8176 warps
// (2x the warp count of the ILP-2 version; 6 front-batched loads/thread).
template<int SRC>
__global__ void __launch_bounds__(128) k_iter1(int nm1) {
    int pj = blockIdx.x * blockDim.x + threadIdx.x;
    int pi = blockIdx.y;
    if (pj >= nm1) return;
    int sp = nm1 + 2;
    int p = pi * nm1 + pj;
    int q = (pi + 1) * sp + (pj + 1);

    const uint2* __restrict__ in0 = g_Mh[SRC][0];
    const uint2* __restrict__ in1 = g_Mh[SRC][1];
    const uint2* __restrict__ in2 = g_Mh[SRC][2];
    const uint2* __restrict__ in3 = g_Mh[SRC][3];
    uint2 r0 = __ldg(&in1[q - sp]);
    uint2 r1 = __ldg(&in0[q + sp]);
    uint2 r2 = __ldg(&in3[q - 1]);
    uint2 r3 = __ldg(&in2[q + 1]);
    uint4 p0 = __ldg(&g_psi[0][p]);
    uint4 p1 = __ldg(&g_psi[1][p]);

    float Phi[16];
    psi_unpack_regs(p0, p1, Phi);
    constexpr int DST = SRC ^ 1;
    plaq_update(h4_to_f4(r0), h4_to_f4(r1), h4_to_f4(r2), h4_to_f4(r3),
                Phi, DST, q);
}

// ---------------------------------------------------------------------------
__device__ __forceinline__ void first_plaq(
    const float4* __restrict__ lpp, int p,
    float4 l0, float4 l1, float4 l2, float4 l3, int q)
{
    float a0[4] = {l0.x, l0.y, l0.z, l0.w};
    float a1[4] = {l1.x, l1.y, l1.z, l1.w};
    float a2[4] = {l2.x, l2.y, l2.z, l2.w};
    float a3[4] = {l3.x, l3.y, l3.z, l3.w};
    float lp[16];
    {
        float4 v;
        v = __ldg(&lpp[p*4+0]); lp[0]=v.x; lp[1]=v.y; lp[2]=v.z; lp[3]=v.w;
        v = __ldg(&lpp[p*4+1]); lp[4]=v.x; lp[5]=v.y; lp[6]=v.z; lp[7]=v.w;
        v = __ldg(&lpp[p*4+2]); lp[8]=v.x; lp[9]=v.y; lp[10]=v.z; lp[11]=v.w;
        v = __ldg(&lpp[p*4+3]); lp[12]=v.x; lp[13]=v.y; lp[14]=v.z; lp[15]=v.w;
    }
    float Phi[16];
    #pragma unroll
    for (int a = 0; a < 2; a++)
    #pragma unroll
    for (int b = 0; b < 2; b++)
    #pragma unroll
    for (int c = 0; c < 2; c++)
    #pragma unroll
    for (int d = 0; d < 2; d++) {
        int idx = a * 8 + b * 4 + c * 2 + d;
        Phi[idx] = __expf(lp[idx] + 0.5f * (a0[a*2+b] + a1[c*2+d]
                                          + a2[a*2+c] + a3[b*2+d]));
    }
    uint2 h0 = f4_to_h4(make_float4(Phi[0],  Phi[1],  Phi[2],  Phi[3]));
    uint2 h1 = f4_to_h4(make_float4(Phi[4],  Phi[5],  Phi[6],  Phi[7]));
    uint2 h2 = f4_to_h4(make_float4(Phi[8],  Phi[9],  Phi[10], Phi[11]));
    uint2 h3 = f4_to_h4(make_float4(Phi[12], Phi[13], Phi[14], Phi[15]));
    g_psi[0][p] = make_uint4(h0.x, h0.y, h1.x, h1.y);
    g_psi[1][p] = make_uint4(h2.x, h2.y, h3.x, h3.y);
    plaq_update(exph4f(l0), exph4f(l1), exph4f(l2), exph4f(l3), Phi, 0, q);
}

// Fused setup + iteration 1 -> buf 0.  Last grid.y row: pads + counters.
__global__ void __launch_bounds__(128) k_first(
    const float4* __restrict__ lpp, const float4* __restrict__ lpe, int nm1)
{
    int sp = nm1 + 2;
    int n = nm1 + 1, nH = n * nm1;
    if (blockIdx.y == gridDim.y - 1) {
        int t = blockIdx.x * blockDim.x + threadIdx.x;
        int tot = gridDim.x * blockDim.x;
        if (t == 0) { g_F = 0.0; g_ctr = 0u; }
        for (int c = t; c < nm1; c += tot) {
            uint2 top = f4_to_h4(exph4f(__ldg(&lpe[c])));
            uint2 bot = f4_to_h4(exph4f(__ldg(&lpe[nm1 * nm1 + c])));
            uint2 lef = f4_to_h4(exph4f(__ldg(&lpe[nH + c * n])));
            uint2 rig = f4_to_h4(exph4f(__ldg(&lpe[nH + c * n + nm1])));
            #pragma unroll
            for (int b = 0; b < 2; b++) {
                g_Mh[b][1][c + 1] = top;                       // row 0 pad
                g_Mh[b][0][(nm1 + 1) * sp + c + 1] = bot;      // bottom pad
                g_Mh[b][3][(c + 1) * sp] = lef;                // left col pad
                g_Mh[b][2][(c + 1) * sp + nm1 + 1] = rig;      // right col pad
            }
        }
        return;
    }

    int pj = blockIdx.x * blockDim.x + threadIdx.x;
    int i0 = blockIdx.y * 2;
    if (pj >= nm1) return;
    bool iok = (i0 + 1) < nm1;
    int i1 = iok ? i0 + 1 : i0;

    float4 lT  = __ldg(&lpe[i0 * nm1 + pj]);
    float4 lM  = __ldg(&lpe[(i0 + 1) * nm1 + pj]);
    float4 lB  = iok ? __ldg(&lpe[(i0 + 2) * nm1 + pj]) : lM;
    float4 lLA = __ldg(&lpe[nH + i0 * n + pj]);
    float4 lRA = __ldg(&lpe[nH + i0 * n + pj + 1]);
    float4 lLB = iok ? __ldg(&lpe[nH + i1 * n + pj]) : lLA;
    float4 lRB = iok ? __ldg(&lpe[nH + i1 * n + pj + 1]) : lRA;

    first_plaq(lpp, i0 * nm1 + pj, lT, lM, lLA, lRA, (i0 + 1) * sp + pj + 1);
    if (iok)
        first_plaq(lpp, i1 * nm1 + pj, lM, lB, lLB, lRB, (i1 + 1) * sp + pj + 1);
}

// ---------------------------------------------------------------------------
// Fully fused finals (reads buf0): edge beliefs, plaquette F term, unary
// marginals; last finished block writes out[0] = -F.
__global__ void k_final(int nm1, const float4* __restrict__ lpe,
                        float* __restrict__ out) {
    int j = blockIdx.x * blockDim.x + threadIdx.x;
    int i = blockIdx.y;
    int n = nm1 + 1, sp = nm1 + 2, nH = n * nm1;
    float fterm = 0.0f;
    if (j < n) {
        int q = (i + 1) * sp + j + 1;
        float4 m_h0 = h4_to_f4(__ldg(&g_Mh[0][0][q]));
        float4 m_h1 = h4_to_f4(__ldg(&g_Mh[0][1][q - sp]));
        float4 m_v0 = h4_to_f4(__ldg(&g_Mh[0][2][q]));
        float4 m_v1 = h4_to_f4(__ldg(&g_Mh[0][3][q - 1]));
        int outB = 1 + 2 * n * n;

        float s0 = 0.f, s1 = 0.f;
        int deg = 0;

        float4 lpH = make_float4(0.f, 0.f, 0.f, 0.f);
        float4 lpV = make_float4(0.f, 0.f, 0.f, 0.f);
        if (j < nm1) {
            int e = i * nm1 + j;
            lpH = __ldg(&lpe[e]);
            float tx = m_h0.x * m_h1.x, ty = m_h0.y * m_h1.y;
            float tz = m_h0.z * m_h1.z, tw = m_h0.w * m_h1.w;
            float Z = (tx + ty) + (tz + tw);
            float inv = __fdividef(1.0f, Z);
            float bx = tx * inv, by = ty * inv, bz = tz * inv, bw = tw * inv;
            int base = outB + e * 4;
            out[base + 0] = bx; out[base + 1] = by; out[base + 2] = bz; out[base + 3] = bw;
            s0 += bx + by; s1 += bz + bw; deg++;
            if (i > 0 && i < nm1) {
                fterm -= bx * (fast_logf(tx) - lpH.x) + by * (fast_logf(ty) - lpH.y)
                       + bz * (fast_logf(tz) - lpH.z) + bw * (fast_logf(tw) - lpH.w)
                       - fast_logf(Z);
            }
        }
        if (j > 0) {
            float4 a = h4_to_f4(__ldg(&g_Mh[0][0][q - 1]));
            float4 b = h4_to_f4(__ldg(&g_Mh[0][1][q - sp - 1]));
            float tx = a.x * b.x, ty = a.y * b.y, tz = a.z * b.z, tw = a.w * b.w;
            float inv = __fdividef(1.0f, (tx + ty) + (tz + tw));
            s0 += (tx + tz) * inv; s1 += (ty + tw) * inv; deg++;
        }
        if (i < nm1) {
            int e = nH + i * n + j;
            lpV = __ldg(&lpe[e]);
            float tx = m_v0.x * m_v1.x, ty = m_v0.y * m_v1.y;
            float tz = m_v0.z * m_v1.z, tw = m_v0.w * m_v1.w;
            float Z = (tx + ty) + (tz + tw);
            float inv = __fdividef(1.0f, Z);
            float bx = tx * inv, by = ty * inv, bz = tz * inv, bw = tw * inv;
            int base = outB + e * 4;
            out[base + 0] = bx; out[base + 1] = by; out[base + 2] = bz; out[base + 3] = bw;
            s0 += bx + by; s1 += bz + bw; deg++;
            if (j > 0 && j < nm1) {
                fterm -= bx * (fast_logf(tx) - lpV.x) + by * (fast_logf(ty) - lpV.y)
                       + bz * (fast_logf(tz) - lpV.z) + bw * (fast_logf(tw) - lpV.w)
                       - fast_logf(Z);
            }
        }
        if (i > 0) {
            float4 a = h4_to_f4(__ldg(&g_Mh[0][2][q - sp]));
            float4 b = h4_to_f4(__ldg(&g_Mh[0][3][q - sp - 1]));
            float tx = a.x * b.x, ty = a.y * b.y, tz = a.z * b.z, tw = a.w * b.w;
            float inv = __fdividef(1.0f, (tx + ty) + (tz + tw));
            s0 += (tx + tz) * inv; s1 += (ty + tw) * inv; deg++;
        }
        {
            float invd = __fdividef(1.0f, (float)deg);
            int v = i * n + j;
            out[1 + v * 2 + 0] = s0 * invd;
            out[1 + v * 2 + 1] = s1 * invd;
        }

        if (i < nm1 && j < nm1) {
            int p = i * nm1 + j;
            float4 x0 = m_h1;
            float4 x1 = h4_to_f4(__ldg(&g_Mh[0][0][q + sp]));
            float4 x2 = m_v1;
            float4 x3 = h4_to_f4(__ldg(&g_Mh[0][2][q + 1]));
            float4 sq0 = exph4f(lpH);
            float4 sq1 = exph4f(__ldg(&lpe[(i + 1) * nm1 + j]));
            float4 sq2 = exph4f(lpV);
            float4 sq3 = exph4f(__ldg(&lpe[nH + i * n + j + 1]));
            float4 Nn0 = mul4(sq0, x0), Nn1 = mul4(sq1, x1);
            float4 Nn2 = mul4(sq2, x2), Nn3 = mul4(sq3, x3);
            float xa[4] = {x0.x, x0.y, x0.z, x0.w};
            float xb[4] = {x1.x, x1.y, x1.z, x1.w};
            float xc[4] = {x2.x, x2.y, x2.z, x2.w};
            float xd[4] = {x3.x, x3.y, x3.z, x3.w};
            float n0[4] = {Nn0.x, Nn0.y, Nn0.z, Nn0.w};
            float n1[4] = {Nn1.x, Nn1.y, Nn1.z, Nn1.w};
            float n2[4] = {Nn2.x, Nn2.y, Nn2.z, Nn2.w};
            float n3[4] = {Nn3.x, Nn3.y, Nn3.z, Nn3.w};
            float Phi[16];
            psi_unpack(p, Phi);

            float t0[4] = {0,0,0,0}, t1[4] = {0,0,0,0}, t2[4] = {0,0,0,0}, t3[4] = {0,0,0,0};
            #pragma unroll
            for (int a = 0; a < 2; a++)
            #pragma unroll
            for (int b = 0; b < 2; b++)
            #pragma unroll
            for (int c = 0; c < 2; c++)
            #pragma unroll
            for (int d = 0; d < 2; d++) {
                int idx = a * 8 + b * 4 + c * 2 + d;
                float ev = Phi[idx] * xa[a * 2 + b] * xb[c * 2 + d]
                                    * xc[a * 2 + c] * xd[b * 2 + d];
                t0[a * 2 + b] += ev; t1[c * 2 + d] += ev;
                t2[a * 2 + c] += ev; t3[b * 2 + d] += ev;
            }
            float sumE = (t0[0] + t0[1]) + (t0[2] + t0[3]);
            float acc = 0.0f;
            #pragma unroll
            for (int x = 0; x < 4; x++) {
                acc = fmaf(t0[x], fast_logf(n0[x]), acc);
                acc = fmaf(t1[x], fast_logf(n1[x]), acc);
                acc = fmaf(t2[x], fast_logf(n2[x]), acc);
                acc = fmaf(t3[x], fast_logf(n3[x]), acc);
            }
            fterm += __fdividef(acc, sumE) - fast_logf(sumE);
        }
    }
    block_add_F(fterm);

    __syncthreads();
    if (threadIdx.x == 0) {
        __threadfence();
        unsigned total = gridDim.x * gridDim.y;
        unsigned old = atomicAdd(&g_ctr, 1u);
        if (old == total - 1) {
            double F = atomicAdd(&g_F, 0.0);
            out[0] = (float)(-F);
        }
    }
}

// ---------------------------------------------------------------------------
extern "C" void kernel_launch(void* const* d_in, const int* in_sizes, int n_in,
                              void* d_out, int out_size) {
    const float* log_phi_plaq = (const float*)d_in[0];
    const float* log_phi_edge = (const float*)d_in[1];

    int P = in_sizes[0] / 16;
    int nm1 = (int)lrint(sqrt((double)P));
    int n = nm1 + 1;
    (void)n_in; (void)out_size;
    float* out = (float*)d_out;

    dim3 bs(128);
    dim3 grF((nm1 + 127) / 128, (nm1 + 1) / 2 + 1);  // +1 row for pads
    dim3 gr1((nm1 + 127) / 128, nm1);                // ILP-1: one row per y

    // iter 1 (fused with setup) -> buf 0
    k_first<<<grF, bs>>>((const float4*)log_phi_plaq, (const float4*)log_phi_edge, nm1);
    // iters 2..5: 0->1, 1->0, 0->1, 1->0  (final state in buf 0)
    k_iter1<0><<<gr1, bs>>>(nm1);
    k_iter1<1><<<gr1, bs>>>(nm1);
    k_iter1<0><<<gr1, bs>>>(nm1);
    k_iter1<1><<<gr1, bs>>>(nm1);
    // finals (+ unary marginals + F write)
    k_final<<<dim3((n + 127) / 128, n), 128>>>(nm1, (const float4*)log_phi_edge, out);
}

// round 15
// speedup vs baseline: 1.0057x; 1.0057x over previous
#include <cuda_runtime.h>
#include <cuda_fp16.h>
#include <math.h>

#define MAXNM1 511
#define MAXSP  (MAXNM1 + 2)
#define MAXSP2 (MAXSP * MAXSP)
#define MAXP   (MAXNM1 * MAXNM1)

// fp16 storage, fp32 compute.
// Messages stored PREMULTIPLIED by sqrt(phiE):  x = sqrt(phiE)*m (pow2-normed).
// Psi = phiP * prod_s sqrt(phiE_s);  u_s = sum E/x_s is already in the stored
// convention -> iterations carry NO edge-phi traffic. Pads hold sqrt(phiE).
//
// PAIRED-PLANE layout (LSU-instruction reduction): record q of g_M01 packs
// (slot0 | slot1) as 16B; g_M23 packs (slot2 | slot3). Writers use 2 STG.128
// per plaquette (was 4 STG.64); readers fetch the needed 8B half.
__device__ uint4 g_M01[2][MAXSP2];
__device__ uint4 g_M23[2][MAXSP2];
__device__ uint4 g_psi[2][MAXP];       // Psi as halves (8 states per entry)
__device__ double g_F;
__device__ unsigned g_ctr;

// ---------------------------------------------------------------------------
__device__ __forceinline__ float4 h4_to_f4(uint2 v) {
    union { unsigned u; __half2 h; } a, b;
    a.u = v.x; b.u = v.y;
    float2 fa = __half22float2(a.h), fb = __half22float2(b.h);
    return make_float4(fa.x, fa.y, fb.x, fb.y);
}
__device__ __forceinline__ uint2 f4_to_h4(float4 f) {
    union { unsigned u; __half2 h; } a, b;
    a.h = __floats2half2_rn(f.x, f.y);
    b.h = __floats2half2_rn(f.z, f.w);
    return make_uint2(a.u, b.u);
}
__device__ __forceinline__ uint2 lo4(uint4 v) { return make_uint2(v.x, v.y); }
__device__ __forceinline__ uint2 hi4(uint4 v) { return make_uint2(v.z, v.w); }

__device__ __forceinline__ float fast_logf(float x) {
    int ix = __float_as_int(x);
    int ex = (ix >> 23) - 127;
    float m = __int_as_float((ix & 0x007FFFFF) | 0x3F800000);
    if (m > 1.41421356f) { m *= 0.5f; ex += 1; }
    float f = m - 1.0f;
    float z = f * f;
    float p = 7.0376836292e-2f;
    p = fmaf(p, f, -1.1514610310e-1f);
    p = fmaf(p, f,  1.1676998740e-1f);
    p = fmaf(p, f, -1.2420140846e-1f);
    p = fmaf(p, f,  1.4249322787e-1f);
    p = fmaf(p, f, -1.6668057665e-1f);
    p = fmaf(p, f,  2.0000714765e-1f);
    p = fmaf(p, f, -2.4999993993e-1f);
    p = fmaf(p, f,  3.3333331174e-1f);
    p = p * z * f;
    p = fmaf(-0.5f, z, p);
    return fmaf((float)ex, 0.693147180559945f, f + p);
}

__device__ __forceinline__ float pow2_inv_scale(float Z) {
    int eb = (__float_as_int(Z) >> 23) & 0xFF;
    return __int_as_float((254 - eb) << 23);
}

__device__ __forceinline__ void block_add_F(float v) {
    #pragma unroll
    for (int o = 16; o; o >>= 1) v += __shfl_down_sync(0xffffffffu, v, o);
    __shared__ float sh[32];
    int lane = threadIdx.x & 31, w = threadIdx.x >> 5;
    if (lane == 0) sh[w] = v;
    __syncthreads();
    if (w == 0) {
        int nw = (blockDim.x + 31) >> 5;
        float s = (lane < nw) ? sh[lane] : 0.0f;
        #pragma unroll
        for (int o = 16; o; o >>= 1) s += __shfl_down_sync(0xffffffffu, s, o);
        if (lane == 0) atomicAdd(&g_F, (double)s);
    }
}

__device__ __forceinline__ float4 mul4(float4 a, float4 b) {
    return make_float4(a.x * b.x, a.y * b.y, a.z * b.z, a.w * b.w);
}
__device__ __forceinline__ float4 exph4f(float4 v) {
    return make_float4(__expf(0.5f * v.x), __expf(0.5f * v.y),
                       __expf(0.5f * v.z), __expf(0.5f * v.w));
}

__device__ __forceinline__ void psi_unpack_regs(uint4 q0, uint4 q1, float Phi[16]) {
    float4 a = h4_to_f4(make_uint2(q0.x, q0.y));
    float4 b = h4_to_f4(make_uint2(q0.z, q0.w));
    float4 c = h4_to_f4(make_uint2(q1.x, q1.y));
    float4 d = h4_to_f4(make_uint2(q1.z, q1.w));
    Phi[0]=a.x; Phi[1]=a.y; Phi[2]=a.z; Phi[3]=a.w;
    Phi[4]=b.x; Phi[5]=b.y; Phi[6]=b.z; Phi[7]=b.w;
    Phi[8]=c.x; Phi[9]=c.y; Phi[10]=c.z; Phi[11]=c.w;
    Phi[12]=d.x; Phi[13]=d.y; Phi[14]=d.z; Phi[15]=d.w;
}
__device__ __forceinline__ void psi_unpack(int p, float Phi[16]) {
    psi_unpack_regs(__ldg(&g_psi[0][p]), __ldg(&g_psi[1][p]), Phi);
}

// Core 16-state update: cavity x0..x3 + Psi -> 2 packed 16B message records.
__device__ __forceinline__ void plaq_update(
    float4 N0, float4 N1, float4 N2, float4 N3, const float Phi[16],
    int dst, int q)
{
    float n0[4] = {N0.x, N0.y, N0.z, N0.w};
    float n1[4] = {N1.x, N1.y, N1.z, N1.w};
    float n2[4] = {N2.x, N2.y, N2.z, N2.w};
    float n3[4] = {N3.x, N3.y, N3.z, N3.w};
    float u0[4] = {0,0,0,0}, u1[4] = {0,0,0,0}, u2[4] = {0,0,0,0}, u3[4] = {0,0,0,0};
    #pragma unroll
    for (int a = 0; a < 2; a++)
    #pragma unroll
    for (int b = 0; b < 2; b++)
    #pragma unroll
    for (int c = 0; c < 2; c++)
    #pragma unroll
    for (int d = 0; d < 2; d++) {
        int idx = a * 8 + b * 4 + c * 2 + d;
        float ph = Phi[idx];
        float va = n0[a * 2 + b], vb = n1[c * 2 + d];
        float vc = n2[a * 2 + c], vd = n3[b * 2 + d];
        float q1 = ph * vc * vd;
        u0[a * 2 + b] = fmaf(q1, vb, u0[a * 2 + b]);
        u1[c * 2 + d] = fmaf(q1, va, u1[c * 2 + d]);
        float q2 = ph * va * vb;
        u2[a * 2 + c] = fmaf(q2, vd, u2[a * 2 + c]);
        u3[b * 2 + d] = fmaf(q2, vc, u3[b * 2 + d]);
    }
    uint2 m0, m1, m2, m3;
    {
        float Z = (u0[0]+u0[1]) + (u0[2]+u0[3]); float s = pow2_inv_scale(Z);
        m0 = f4_to_h4(make_float4(u0[0]*s, u0[1]*s, u0[2]*s, u0[3]*s));
    }
    {
        float Z = (u1[0]+u1[1]) + (u1[2]+u1[3]); float s = pow2_inv_scale(Z);
        m1 = f4_to_h4(make_float4(u1[0]*s, u1[1]*s, u1[2]*s, u1[3]*s));
    }
    {
        float Z = (u2[0]+u2[1]) + (u2[2]+u2[3]); float s = pow2_inv_scale(Z);
        m2 = f4_to_h4(make_float4(u2[0]*s, u2[1]*s, u2[2]*s, u2[3]*s));
    }
    {
        float Z = (u3[0]+u3[1]) + (u3[2]+u3[3]); float s = pow2_inv_scale(Z);
        m3 = f4_to_h4(make_float4(u3[0]*s, u3[1]*s, u3[2]*s, u3[3]*s));
    }
    g_M01[dst][q] = make_uint4(m0.x, m0.y, m1.x, m1.y);   // STG.128
    g_M23[dst][q] = make_uint4(m2.x, m2.y, m3.x, m3.y);   // STG.128
}

// ---------------------------------------------------------------------------
// ILP-1 iteration: 4x LDG.64 (msg halves) + 2x LDG.128 (Psi) + 2x STG.128.
template<int SRC>
__global__ void __launch_bounds__(128) k_iter1(int nm1) {
    int pj = blockIdx.x * blockDim.x + threadIdx.x;
    int pi = blockIdx.y;
    if (pj >= nm1) return;
    int sp = nm1 + 2;
    int p = pi * nm1 + pj;
    int q = (pi + 1) * sp + (pj + 1);

    const uint2* __restrict__ in01 = (const uint2*)g_M01[SRC];
    const uint2* __restrict__ in23 = (const uint2*)g_M23[SRC];
    uint2 r0 = __ldg(&in01[2 * (q - sp) + 1]);   // slot1 of above
    uint2 r1 = __ldg(&in01[2 * (q + sp)]);       // slot0 of below
    uint2 r2 = __ldg(&in23[2 * (q - 1) + 1]);    // slot3 of left
    uint2 r3 = __ldg(&in23[2 * (q + 1)]);        // slot2 of right
    uint4 p0 = __ldg(&g_psi[0][p]);
    uint4 p1 = __ldg(&g_psi[1][p]);

    float Phi[16];
    psi_unpack_regs(p0, p1, Phi);
    constexpr int DST = SRC ^ 1;
    plaq_update(h4_to_f4(r0), h4_to_f4(r1), h4_to_f4(r2), h4_to_f4(r3),
                Phi, DST, q);
}

// ---------------------------------------------------------------------------
__device__ __forceinline__ void first_plaq(
    const float4* __restrict__ lpp, int p,
    float4 l0, float4 l1, float4 l2, float4 l3, int q)
{
    float a0[4] = {l0.x, l0.y, l0.z, l0.w};
    float a1[4] = {l1.x, l1.y, l1.z, l1.w};
    float a2[4] = {l2.x, l2.y, l2.z, l2.w};
    float a3[4] = {l3.x, l3.y, l3.z, l3.w};
    float lp[16];
    {
        float4 v;
        v = __ldg(&lpp[p*4+0]); lp[0]=v.x; lp[1]=v.y; lp[2]=v.z; lp[3]=v.w;
        v = __ldg(&lpp[p*4+1]); lp[4]=v.x; lp[5]=v.y; lp[6]=v.z; lp[7]=v.w;
        v = __ldg(&lpp[p*4+2]); lp[8]=v.x; lp[9]=v.y; lp[10]=v.z; lp[11]=v.w;
        v = __ldg(&lpp[p*4+3]); lp[12]=v.x; lp[13]=v.y; lp[14]=v.z; lp[15]=v.w;
    }
    float Phi[16];
    #pragma unroll
    for (int a = 0; a < 2; a++)
    #pragma unroll
    for (int b = 0; b < 2; b++)
    #pragma unroll
    for (int c = 0; c < 2; c++)
    #pragma unroll
    for (int d = 0; d < 2; d++) {
        int idx = a * 8 + b * 4 + c * 2 + d;
        Phi[idx] = __expf(lp[idx] + 0.5f * (a0[a*2+b] + a1[c*2+d]
                                          + a2[a*2+c] + a3[b*2+d]));
    }
    uint2 h0 = f4_to_h4(make_float4(Phi[0],  Phi[1],  Phi[2],  Phi[3]));
    uint2 h1 = f4_to_h4(make_float4(Phi[4],  Phi[5],  Phi[6],  Phi[7]));
    uint2 h2 = f4_to_h4(make_float4(Phi[8],  Phi[9],  Phi[10], Phi[11]));
    uint2 h3 = f4_to_h4(make_float4(Phi[12], Phi[13], Phi[14], Phi[15]));
    g_psi[0][p] = make_uint4(h0.x, h0.y, h1.x, h1.y);
    g_psi[1][p] = make_uint4(h2.x, h2.y, h3.x, h3.y);
    plaq_update(exph4f(l0), exph4f(l1), exph4f(l2), exph4f(l3), Phi, 0, q);
}

// Fused setup + iteration 1 -> buf 0.  Last grid.y row: pads + counters.
// Pads write full 16B records with the sqrt(phiE) value duplicated in both
// halves (only the relevant half is ever read).
__global__ void __launch_bounds__(128) k_first(
    const float4* __restrict__ lpp, const float4* __restrict__ lpe, int nm1)
{
    int sp = nm1 + 2;
    int n = nm1 + 1, nH = n * nm1;
    if (blockIdx.y == gridDim.y - 1) {
        int t = blockIdx.x * blockDim.x + threadIdx.x;
        int tot = gridDim.x * blockDim.x;
        if (t == 0) { g_F = 0.0; g_ctr = 0u; }
        for (int c = t; c < nm1; c += tot) {
            uint2 top = f4_to_h4(exph4f(__ldg(&lpe[c])));
            uint2 bot = f4_to_h4(exph4f(__ldg(&lpe[nm1 * nm1 + c])));
            uint2 lef = f4_to_h4(exph4f(__ldg(&lpe[nH + c * n])));
            uint2 rig = f4_to_h4(exph4f(__ldg(&lpe[nH + c * n + nm1])));
            #pragma unroll
            for (int b = 0; b < 2; b++) {
                g_M01[b][c + 1] = make_uint4(top.x, top.y, top.x, top.y);
                g_M01[b][(nm1 + 1) * sp + c + 1] = make_uint4(bot.x, bot.y, bot.x, bot.y);
                g_M23[b][(c + 1) * sp] = make_uint4(lef.x, lef.y, lef.x, lef.y);
                g_M23[b][(c + 1) * sp + nm1 + 1] = make_uint4(rig.x, rig.y, rig.x, rig.y);
            }
        }
        return;
    }

    int pj = blockIdx.x * blockDim.x + threadIdx.x;
    int i0 = blockIdx.y * 2;
    if (pj >= nm1) return;
    bool iok = (i0 + 1) < nm1;
    int i1 = iok ? i0 + 1 : i0;

    float4 lT  = __ldg(&lpe[i0 * nm1 + pj]);
    float4 lM  = __ldg(&lpe[(i0 + 1) * nm1 + pj]);
    float4 lB  = iok ? __ldg(&lpe[(i0 + 2) * nm1 + pj]) : lM;
    float4 lLA = __ldg(&lpe[nH + i0 * n + pj]);
    float4 lRA = __ldg(&lpe[nH + i0 * n + pj + 1]);
    float4 lLB = iok ? __ldg(&lpe[nH + i1 * n + pj]) : lLA;
    float4 lRB = iok ? __ldg(&lpe[nH + i1 * n + pj + 1]) : lRA;

    first_plaq(lpp, i0 * nm1 + pj, lT, lM, lLA, lRA, (i0 + 1) * sp + pj + 1);
    if (iok)
        first_plaq(lpp, i1 * nm1 + pj, lM, lB, lLB, lRB, (i1 + 1) * sp + pj + 1);
}

// ---------------------------------------------------------------------------
// Fully fused finals (reads buf0): edge beliefs, plaquette F term, unary
// marginals; last finished block writes out[0] = -F.
__global__ void k_final(int nm1, const float4* __restrict__ lpe,
                        float* __restrict__ out) {
    int j = blockIdx.x * blockDim.x + threadIdx.x;
    int i = blockIdx.y;
    int n = nm1 + 1, sp = nm1 + 2, nH = n * nm1;
    float fterm = 0.0f;
    if (j < n) {
        int q = (i + 1) * sp + j + 1;
        const uint2* __restrict__ b01 = (const uint2*)g_M01[0];
        const uint2* __restrict__ b23 = (const uint2*)g_M23[0];
        float4 m_h0 = h4_to_f4(__ldg(&b01[2 * q]));            // slot0 @ q
        float4 m_h1 = h4_to_f4(__ldg(&b01[2 * (q - sp) + 1])); // slot1 @ q-sp
        float4 m_v0 = h4_to_f4(__ldg(&b23[2 * q]));            // slot2 @ q
        float4 m_v1 = h4_to_f4(__ldg(&b23[2 * (q - 1) + 1]));  // slot3 @ q-1
        int outB = 1 + 2 * n * n;

        float s0 = 0.f, s1 = 0.f;
        int deg = 0;

        float4 lpH = make_float4(0.f, 0.f, 0.f, 0.f);
        float4 lpV = make_float4(0.f, 0.f, 0.f, 0.f);
        if (j < nm1) {
            int e = i * nm1 + j;
            lpH = __ldg(&lpe[e]);
            float tx = m_h0.x * m_h1.x, ty = m_h0.y * m_h1.y;
            float tz = m_h0.z * m_h1.z, tw = m_h0.w * m_h1.w;
            float Z = (tx + ty) + (tz + tw);
            float inv = __fdividef(1.0f, Z);
            float bx = tx * inv, by = ty * inv, bz = tz * inv, bw = tw * inv;
            int base = outB + e * 4;
            out[base + 0] = bx; out[base + 1] = by; out[base + 2] = bz; out[base + 3] = bw;
            s0 += bx + by; s1 += bz + bw; deg++;
            if (i > 0 && i < nm1) {
                fterm -= bx * (fast_logf(tx) - lpH.x) + by * (fast_logf(ty) - lpH.y)
                       + bz * (fast_logf(tz) - lpH.z) + bw * (fast_logf(tw) - lpH.w)
                       - fast_logf(Z);
            }
        }
        if (j > 0) {        // h-edge (i,j-1): node var1 contrib
            float4 a = h4_to_f4(__ldg(&b01[2 * (q - 1)]));          // slot0 @ q-1
            float4 b = h4_to_f4(__ldg(&b01[2 * (q - sp - 1) + 1])); // slot1 @ q-sp-1
            float tx = a.x * b.x, ty = a.y * b.y, tz = a.z * b.z, tw = a.w * b.w;
            float inv = __fdividef(1.0f, (tx + ty) + (tz + tw));
            s0 += (tx + tz) * inv; s1 += (ty + tw) * inv; deg++;
        }
        if (i < nm1) {
            int e = nH + i * n + j;
            lpV = __ldg(&lpe[e]);
            float tx = m_v0.x * m_v1.x, ty = m_v0.y * m_v1.y;
            float tz = m_v0.z * m_v1.z, tw = m_v0.w * m_v1.w;
            float Z = (tx + ty) + (tz + tw);
            float inv = __fdividef(1.0f, Z);
            float bx = tx * inv, by = ty * inv, bz = tz * inv, bw = tw * inv;
            int base = outB + e * 4;
            out[base + 0] = bx; out[base + 1] = by; out[base + 2] = bz; out[base + 3] = bw;
            s0 += bx + by; s1 += bz + bw; deg++;
            if (j > 0 && j < nm1) {
                fterm -= bx * (fast_logf(tx) - lpV.x) + by * (fast_logf(ty) - lpV.y)
                       + bz * (fast_logf(tz) - lpV.z) + bw * (fast_logf(tw) - lpV.w)
                       - fast_logf(Z);
            }
        }
        if (i > 0) {        // v-edge (i-1,j): node var1 contrib
            float4 a = h4_to_f4(__ldg(&b23[2 * (q - sp)]));         // slot2 @ q-sp
            float4 b = h4_to_f4(__ldg(&b23[2 * (q - sp - 1) + 1])); // slot3 @ q-sp-1
            float tx = a.x * b.x, ty = a.y * b.y, tz = a.z * b.z, tw = a.w * b.w;
            float inv = __fdividef(1.0f, (tx + ty) + (tz + tw));
            s0 += (tx + tz) * inv; s1 += (ty + tw) * inv; deg++;
        }
        {
            float invd = __fdividef(1.0f, (float)deg);
            int v = i * n + j;
            out[1 + v * 2 + 0] = s0 * invd;
            out[1 + v * 2 + 1] = s1 * invd;
        }

        if (i < nm1 && j < nm1) {
            int p = i * nm1 + j;
            float4 x0 = m_h1;
            float4 x1 = h4_to_f4(__ldg(&b01[2 * (q + sp)]));    // slot0 @ q+sp
            float4 x2 = m_v1;
            float4 x3 = h4_to_f4(__ldg(&b23[2 * (q + 1)]));     // slot2 @ q+1
            float4 sq0 = exph4f(lpH);
            float4 sq1 = exph4f(__ldg(&lpe[(i + 1) * nm1 + j]));
            float4 sq2 = exph4f(lpV);
            float4 sq3 = exph4f(__ldg(&lpe[nH + i * n + j + 1]));
            float4 Nn0 = mul4(sq0, x0), Nn1 = mul4(sq1, x1);
            float4 Nn2 = mul4(sq2, x2), Nn3 = mul4(sq3, x3);
            float xa[4] = {x0.x, x0.y, x0.z, x0.w};
            float xb[4] = {x1.x, x1.y, x1.z, x1.w};
            float xc[4] = {x2.x, x2.y, x2.z, x2.w};
            float xd[4] = {x3.x, x3.y, x3.z, x3.w};
            float n0[4] = {Nn0.x, Nn0.y, Nn0.z, Nn0.w};
            float n1[4] = {Nn1.x, Nn1.y, Nn1.z, Nn1.w};
            float n2[4] = {Nn2.x, Nn2.y, Nn2.z, Nn2.w};
            float n3[4] = {Nn3.x, Nn3.y, Nn3.z, Nn3.w};
            float Phi[16];
            psi_unpack(p, Phi);

            float t0[4] = {0,0,0,0}, t1[4] = {0,0,0,0}, t2[4] = {0,0,0,0}, t3[4] = {0,0,0,0};
            #pragma unroll
            for (int a = 0; a < 2; a++)
            #pragma unroll
            for (int b = 0; b < 2; b++)
            #pragma unroll
            for (int c = 0; c < 2; c++)
            #pragma unroll
            for (int d = 0; d < 2; d++) {
                int idx = a * 8 + b * 4 + c * 2 + d;
                float ev = Phi[idx] * xa[a * 2 + b] * xb[c * 2 + d]
                                    * xc[a * 2 + c] * xd[b * 2 + d];
                t0[a * 2 + b] += ev; t1[c * 2 + d] += ev;
                t2[a * 2 + c] += ev; t3[b * 2 + d] += ev;
            }
            float sumE = (t0[0] + t0[1]) + (t0[2] + t0[3]);
            float acc = 0.0f;
            #pragma unroll
            for (int x = 0; x < 4; x++) {
                acc = fmaf(t0[x], fast_logf(n0[x]), acc);
                acc = fmaf(t1[x], fast_logf(n1[x]), acc);
                acc = fmaf(t2[x], fast_logf(n2[x]), acc);
                acc = fmaf(t3[x], fast_logf(n3[x]), acc);
            }
            fterm += __fdividef(acc, sumE) - fast_logf(sumE);
        }
    }
    block_add_F(fterm);

    __syncthreads();
    if (threadIdx.x == 0) {
        __threadfence();
        unsigned total = gridDim.x * gridDim.y;
        unsigned old = atomicAdd(&g_ctr, 1u);
        if (old == total - 1) {
            double F = atomicAdd(&g_F, 0.0);
            out[0] = (float)(-F);
        }
    }
}

// ---------------------------------------------------------------------------
extern "C" void kernel_launch(void* const* d_in, const int* in_sizes, int n_in,
                              void* d_out, int out_size) {
    const float* log_phi_plaq = (const float*)d_in[0];
    const float* log_phi_edge = (const float*)d_in[1];

    int P = in_sizes[0] / 16;
    int nm1 = (int)lrint(sqrt((double)P));
    int n = nm1 + 1;
    (void)n_in; (void)out_size;
    float* out = (float*)d_out;

    dim3 bs(128);
    dim3 grF((nm1 + 127) / 128, (nm1 + 1) / 2 + 1);  // +1 row for pads
    dim3 gr1((nm1 + 127) / 128, nm1);                // ILP-1: one row per y

    // iter 1 (fused with setup) -> buf 0
    k_first<<<grF, bs>>>((const float4*)log_phi_plaq, (const float4*)log_phi_edge, nm1);
    // iters 2..5: 0->1, 1->0, 0->1, 1->0  (final state in buf 0)
    k_iter1<0><<<gr1, bs>>>(nm1);
    k_iter1<1><<<gr1, bs>>>(nm1);
    k_iter1<0><<<gr1, bs>>>(nm1);
    k_iter1<1><<<gr1, bs>>>(nm1);
    // finals (+ unary marginals + F write)
    k_final<<<dim3((n + 127) / 128, n), 128>>>(nm1, (const float4*)log_phi_edge, out);
}